// round 1
// baseline (speedup 1.0000x reference)
#include <cuda_runtime.h>
#include <cuda_bf16.h>
#include <math.h>

// Problem constants (fixed by the dataset)
#define TOK   1024          // B*S = 2*512
#define D     1024          // hidden dim
#define HQ    2048          // H*QD
#define HEADS 8
#define QD    256
#define HALF  128
#define NK    32            // keys per axis
#define DTK   4
#define NEXP  128           // HEADS * DTK*DTK per token
#define E     1024          // experts
#define O     1024          // out dim

// ---------------- scratch (device globals; no allocation allowed) -----------
__device__ float g_q[TOK * HQ];        // 8 MB
__device__ float g_sums[QD];
__device__ float g_sqs[QD];
__device__ float g_mean[QD];
__device__ float g_rstd[QD];
__device__ float g_k0n[NK * HALF];
__device__ float g_k1n[NK * HALF];
__device__ int   g_idx[TOK * NEXP];
__device__ float g_w[TOK * NEXP];

// ---------------- Kernel 1: q = hidden @ Wq + bq  ---------------------------
// 128x128 tile, BK=8, 256 threads, 8x8 per thread.
__global__ __launch_bounds__(256, 2)
void gemm_q_kernel(const float* __restrict__ A,   // [TOK, D]
                   const float* __restrict__ W,   // [D, HQ]
                   const float* __restrict__ bq)  // [HQ]
{
    __shared__ float As[8][128];
    __shared__ float Bs[8][128];

    const int bx = blockIdx.x;        // N tile (16)
    const int by = blockIdx.y;        // M tile (8)
    const int tid = threadIdx.x;
    const int tx = tid & 15;          // 0..15
    const int ty = tid >> 4;          // 0..15

    float acc[8][8];
    #pragma unroll
    for (int i = 0; i < 8; i++)
        #pragma unroll
        for (int j = 0; j < 8; j++) acc[i][j] = 0.f;

    const int aRow = tid >> 1;            // 0..127
    const int aK4  = (tid & 1) * 4;       // 0 or 4
    const int bK   = tid >> 5;            // 0..7
    const int bN4  = (tid & 31) * 4;      // 0..124

    const float* Ab = A + (size_t)by * 128 * D;
    const float* Wb = W + (size_t)bx * 128;

    for (int k0 = 0; k0 < D; k0 += 8) {
        float4 a4 = *(const float4*)(Ab + (size_t)aRow * D + k0 + aK4);
        As[aK4 + 0][aRow] = a4.x;
        As[aK4 + 1][aRow] = a4.y;
        As[aK4 + 2][aRow] = a4.z;
        As[aK4 + 3][aRow] = a4.w;
        float4 b4 = *(const float4*)(Wb + (size_t)(k0 + bK) * HQ + bN4);
        *(float4*)(&Bs[bK][bN4]) = b4;
        __syncthreads();

        #pragma unroll
        for (int k = 0; k < 8; k++) {
            float ra[8], rb[8];
            #pragma unroll
            for (int i = 0; i < 8; i++) ra[i] = As[k][ty * 8 + i];
            #pragma unroll
            for (int j = 0; j < 8; j++) rb[j] = Bs[k][tx * 8 + j];
            #pragma unroll
            for (int i = 0; i < 8; i++)
                #pragma unroll
                for (int j = 0; j < 8; j++)
                    acc[i][j] = fmaf(ra[i], rb[j], acc[i][j]);
        }
        __syncthreads();
    }

    #pragma unroll
    for (int i = 0; i < 8; i++) {
        int row = by * 128 + ty * 8 + i;
        #pragma unroll
        for (int j = 0; j < 8; j += 4) {
            int col = bx * 128 + tx * 8 + j;
            float4 v;
            v.x = acc[i][j + 0] + bq[col + 0];
            v.y = acc[i][j + 1] + bq[col + 1];
            v.z = acc[i][j + 2] + bq[col + 2];
            v.w = acc[i][j + 3] + bq[col + 3];
            *(float4*)(&g_q[(size_t)row * HQ + col]) = v;
        }
    }
}

// ---------------- Kernel 2a: zero stats -------------------------------------
__global__ void zero_stats_kernel() {
    int t = threadIdx.x;
    if (t < QD) { g_sums[t] = 0.f; g_sqs[t] = 0.f; }
}

// ---------------- Kernel 2b: per-feature partial sums -----------------------
// grid 16, block 256. feature = tid; each block handles 64 token-rows.
__global__ void stats_partial_kernel() {
    const int tid = threadIdx.x;        // feature id 0..255
    const int rowStart = blockIdx.x * 64;
    float s = 0.f, sq = 0.f;
    for (int r = 0; r < 64; r++) {
        const float* row = g_q + (size_t)(rowStart + r) * HQ;
        #pragma unroll
        for (int h = 0; h < HEADS; h++) {
            float v = row[h * QD + tid];
            s += v; sq += v * v;
        }
    }
    atomicAdd(&g_sums[tid], s);
    atomicAdd(&g_sqs[tid], sq);
}

// ---------------- Kernel 2c: finalize mean / rstd ---------------------------
__global__ void finalize_stats_kernel() {
    int t = threadIdx.x;
    if (t < QD) {
        const float invN = 1.0f / (float)(TOK * HEADS);
        float m = g_sums[t] * invN;
        float var = g_sqs[t] * invN - m * m;
        g_mean[t] = m;
        g_rstd[t] = rsqrtf(var + 1e-5f);
    }
}

// ---------------- Kernel 2d: L2-normalize sub-keys --------------------------
// grid 64 (32 rows of k0 then 32 of k1), block 128.
__global__ void norm_keys_kernel(const float* __restrict__ k0,
                                 const float* __restrict__ k1) {
    const int row = blockIdx.x;
    const int tid = threadIdx.x;
    const float* src = (row < NK) ? (k0 + (size_t)row * HALF)
                                  : (k1 + (size_t)(row - NK) * HALF);
    float* dst = (row < NK) ? (g_k0n + (size_t)row * HALF)
                            : (g_k1n + (size_t)(row - NK) * HALF);
    __shared__ float red[128];
    float v = src[tid];
    red[tid] = v * v;
    __syncthreads();
    for (int s = 64; s > 0; s >>= 1) {
        if (tid < s) red[tid] += red[tid + s];
        __syncthreads();
    }
    float n = sqrtf(red[0]);
    dst[tid] = v / fmaxf(n, 1e-12f);
}

// ---------------- Kernel 3: BN + L2norm + scores + top4x4 + softmax ---------
// grid TOK*HEADS = 8192, block 128.
__global__ __launch_bounds__(128)
void score_kernel(const float* __restrict__ gamma,
                  const float* __restrict__ beta) {
    const int u = blockIdx.x;           // (token, head) unit
    const int t = u >> 3;
    const int h = u & 7;
    const int tid = threadIdx.x;        // 0..127

    __shared__ float q0[HALF], q1[HALF];
    __shared__ float red0[128], red1[128];
    __shared__ float s0s[NK], s1s[NK];
    __shared__ float ts0[DTK], ts1[DTK];
    __shared__ int   ti0[DTK], ti1[DTK];
    __shared__ float combS[16];
    __shared__ int   combI[16];
    __shared__ float smx, ssum;

    const float* qrow = g_q + (size_t)t * HQ + h * QD;
    float a = qrow[tid];
    float b = qrow[HALF + tid];
    a = (a - g_mean[tid]) * g_rstd[tid] * gamma[tid] + beta[tid];
    b = (b - g_mean[HALF + tid]) * g_rstd[HALF + tid] * gamma[HALF + tid] + beta[HALF + tid];

    red0[tid] = a * a;
    red1[tid] = b * b;
    __syncthreads();
    for (int s = 64; s > 0; s >>= 1) {
        if (tid < s) { red0[tid] += red0[tid + s]; red1[tid] += red1[tid + s]; }
        __syncthreads();
    }
    float n0 = fmaxf(sqrtf(red0[0]), 1e-12f);
    float n1 = fmaxf(sqrtf(red1[0]), 1e-12f);
    q0[tid] = a / n0;
    q1[tid] = b / n1;
    __syncthreads();

    // 32 dots of 128 per axis; 4 warps, 8 dots per warp per axis
    const int w = tid >> 5, l = tid & 31;
    for (int j = w; j < NK; j += 4) {
        const float* kr0 = g_k0n + j * HALF;
        const float* kr1 = g_k1n + j * HALF;
        float d0 = kr0[l] * q0[l] + kr0[l + 32] * q0[l + 32]
                 + kr0[l + 64] * q0[l + 64] + kr0[l + 96] * q0[l + 96];
        float d1 = kr1[l] * q1[l] + kr1[l + 32] * q1[l + 32]
                 + kr1[l + 64] * q1[l + 64] + kr1[l + 96] * q1[l + 96];
        #pragma unroll
        for (int off = 16; off; off >>= 1) {
            d0 += __shfl_down_sync(0xffffffffu, d0, off);
            d1 += __shfl_down_sync(0xffffffffu, d1, off);
        }
        if (l == 0) { s0s[j] = d0; s1s[j] = d1; }
    }
    __syncthreads();

    // top-4 per axis (single thread each, ties -> lowest index like lax.top_k)
    if (tid == 0) {
        float vals[NK];
        for (int i = 0; i < NK; i++) vals[i] = s0s[i];
        for (int p = 0; p < DTK; p++) {
            int bi = 0; float bv = -1e30f;
            for (int i = 0; i < NK; i++) if (vals[i] > bv) { bv = vals[i]; bi = i; }
            ts0[p] = bv; ti0[p] = bi; vals[bi] = -1e30f;
        }
    }
    if (tid == 32) {
        float vals[NK];
        for (int i = 0; i < NK; i++) vals[i] = s1s[i];
        for (int p = 0; p < DTK; p++) {
            int bi = 0; float bv = -1e30f;
            for (int i = 0; i < NK; i++) if (vals[i] > bv) { bv = vals[i]; bi = i; }
            ts1[p] = bv; ti1[p] = bi; vals[bi] = -1e30f;
        }
    }
    __syncthreads();

    // 4x4 cartesian combine; softmax over all 16 (TOPK==16, sort is a no-op
    // for the final permutation-invariant weighted sum)
    if (tid < 16) {
        int i = tid >> 2, j = tid & 3;
        combS[tid] = ts0[i] + ts1[j];
        combI[tid] = ti0[i] * NK + ti1[j];
    }
    __syncthreads();
    if (tid == 0) {
        float m = -1e30f;
        for (int k = 0; k < 16; k++) m = fmaxf(m, combS[k]);
        float s = 0.f;
        for (int k = 0; k < 16; k++) s += expf(combS[k] - m);
        smx = m; ssum = s;
    }
    __syncthreads();
    if (tid < 16) {
        g_idx[(size_t)u * 16 + tid] = combI[tid];
        g_w[(size_t)u * 16 + tid]   = expf(combS[tid] - smx) / ssum;
    }
}

// ---------------- Kernel 4: expert gather + gelu + weighted up-sum ----------
// grid TOK, block 256. L2-bound on gathered expert rows.
__global__ __launch_bounds__(256, 4)
void expert_kernel(const float* __restrict__ hidden,
                   const float* __restrict__ down,   // [E, D]
                   const float* __restrict__ up,     // [E, O]
                   float* __restrict__ out)          // [TOK, O]
{
    const int t = blockIdx.x;
    const int tid = threadIdx.x;
    __shared__ float hs[D];
    __shared__ float coeff[NEXP];
    __shared__ int   eidx[NEXP];

    for (int i = tid; i < D; i += 256) hs[i] = hidden[(size_t)t * D + i];
    if (tid < NEXP) eidx[tid] = g_idx[(size_t)t * NEXP + tid];
    __syncthreads();

    // Phase A: 128 dot products of length 1024; 8 warps x 16 experts
    const int w = tid >> 5, l = tid & 31;
    for (int e = w; e < NEXP; e += 8) {
        const float* drow = down + (size_t)eidx[e] * D;
        float s = 0.f;
        #pragma unroll 8
        for (int d = l; d < D; d += 32) s = fmaf(drow[d], hs[d], s);
        #pragma unroll
        for (int off = 16; off; off >>= 1) s += __shfl_down_sync(0xffffffffu, s, off);
        if (l == 0) {
            float g = 0.5f * s * (1.0f + erff(s * 0.70710678118654752f));
            coeff[e] = g * g_w[(size_t)t * NEXP + e];
        }
    }
    __syncthreads();

    // Phase B: out[o] = sum_e coeff[e] * up[eidx[e]][o]
    const int o = tid * 4;
    float a0 = 0.f, a1 = 0.f, a2 = 0.f, a3 = 0.f;
    #pragma unroll 4
    for (int e = 0; e < NEXP; e++) {
        float c = coeff[e];
        float4 u4 = *(const float4*)(up + (size_t)eidx[e] * O + o);
        a0 = fmaf(c, u4.x, a0);
        a1 = fmaf(c, u4.y, a1);
        a2 = fmaf(c, u4.z, a2);
        a3 = fmaf(c, u4.w, a3);
    }
    float4 r; r.x = a0; r.y = a1; r.z = a2; r.w = a3;
    *(float4*)(out + (size_t)t * O + o) = r;
}

// ---------------- launch ----------------------------------------------------
extern "C" void kernel_launch(void* const* d_in, const int* in_sizes, int n_in,
                              void* d_out, int out_size) {
    const float* hidden = (const float*)d_in[0];   // [2,512,1024]
    const float* Wq     = (const float*)d_in[1];   // [1024,2048]
    const float* bq     = (const float*)d_in[2];   // [2048]
    const float* gamma  = (const float*)d_in[3];   // [256]
    const float* beta   = (const float*)d_in[4];   // [256]
    const float* k0     = (const float*)d_in[5];   // [32,128]
    const float* k1     = (const float*)d_in[6];   // [32,128]
    const float* down   = (const float*)d_in[7];   // [1024,1024]
    const float* up     = (const float*)d_in[8];   // [1024,1024]
    float* out = (float*)d_out;                    // [2,512,1024]

    gemm_q_kernel<<<dim3(HQ / 128, TOK / 128), 256>>>(hidden, Wq, bq);
    zero_stats_kernel<<<1, 256>>>();
    stats_partial_kernel<<<16, 256>>>();
    finalize_stats_kernel<<<1, 256>>>();
    norm_keys_kernel<<<64, 128>>>(k0, k1);
    score_kernel<<<TOK * HEADS, 128>>>(gamma, beta);
    expert_kernel<<<TOK, 256>>>(hidden, down, up, out);
}